// round 14
// baseline (speedup 1.0000x reference)
#include <cuda_runtime.h>

#define T_STEPS 500
#define N_NEUR  20000
#define NGRP    625              // neuron groups of 32 (k=1)
#define NDUP    559              // groups 0..558 get a second warp (1184 = 625 + 559)
#define DT      0.1f
#define UNROLL  10               // 500 = 10 * 50
#define NBLK    (T_STEPS / UNROLL)

__device__ __forceinline__ float fast_tanh(float t) {
    float r;
    asm("tanh.approx.f32 %0, %1;" : "=f"(r) : "f"(t));
    return r;
}

__global__ void __launch_bounds__(32, 8) hh_kernel(
    const float* __restrict__ i_inj,   // [T, N]
    const float* __restrict__ x0,      // [7, N]
    const float* __restrict__ params,  // [28]
    float* __restrict__ out)           // [T, 7, N]
{
    // 1184 one-warp blocks = exactly 8/SM = 2/SMSP (perfectly balanced).
    //   bid <  559        : replica 0 of group bid    (stores V,p,q,n)
    //   559 <= bid < 625  : solo warp of group bid    (stores all 7)
    //   bid >= 625        : replica 1 of group bid-625 (stores e,f,cac)
    const int bid = blockIdx.x;
    int grp, role;                     // 0=rep0, 1=solo, 2=rep1
    if (bid < NGRP) { grp = bid;        role = (bid < NDUP) ? 0 : 1; }
    else            { grp = bid - NGRP; role = 2; }
    const bool store_lo = (role != 2);
    const bool store_hi = (role != 0);

    const int n = grp * 32 + threadIdx.x;   // one neuron per thread (k=1)

    // ---- fold constants (identical on replicas -> identical trajectories)
    const float decay_ca = params[0];
    const float rho_ca   = params[1];
    const float p_tau = params[2],  p_scale = params[3],  p_mdp = params[4];
    const float q_tau = params[5],  q_scale = params[6],  q_mdp = params[7];
    const float n_tau = params[8],  n_scale = params[9],  n_mdp = params[10];
    const float f_tau = params[11], f_scale = params[12], f_mdp = params[13];
    const float e_tau = params[14], e_scale = params[15], e_mdp = params[16];
    const float h_alpha = params[17], h_scale = params[18], h_mdp = params[19];
    const float C_m = params[20], g_Ca = params[21], g_Ks = params[22];
    const float g_Kf = params[23], g_L = params[24];
    const float E_Ca = params[25], E_K = params[26], E_L = params[27];

    const float pc1 = 0.5f / p_scale, pc0 = -p_mdp * 0.5f / p_scale;
    const float qc1 = 0.5f / q_scale, qc0 = -q_mdp * 0.5f / q_scale;
    const float nc1 = 0.5f / n_scale, nc0 = -n_mdp * 0.5f / n_scale;
    const float fc1 = 0.5f / f_scale, fc0 = -f_mdp * 0.5f / f_scale;
    const float ec1 = 0.5f / e_scale, ec0 = -e_mdp * 0.5f / e_scale;
    const float hc1 = 0.5f / h_scale, hc0 = -h_mdp * 0.5f / h_scale;

    const float Ap = p_tau / (p_tau + DT), Bp = 0.5f * DT / (p_tau + DT);
    const float Aq = q_tau / (q_tau + DT), Bq = 0.5f * DT / (q_tau + DT);
    const float An = n_tau / (n_tau + DT), Bn = 0.5f * DT / (n_tau + DT);
    const float Af = f_tau / (f_tau + DT), Bf = 0.5f * DT / (f_tau + DT);
    const float Ae = e_tau / (e_tau + DT), Be = 0.5f * DT / (e_tau + DT);

    const float hb = 0.5f * h_alpha, ha = 1.0f - 0.5f * h_alpha;
    const float dtCm  = DT / C_m;
    const float cdec  = 1.0f - DT / decay_ca;
    const float rhoDt = rho_ca * DT;

    // ---- initial state (R11's per-neuron math, bit-identical)
    float V   = x0[0 * N_NEUR + n];
    float p   = x0[1 * N_NEUR + n];
    float q   = x0[2 * N_NEUR + n];
    float nn  = x0[3 * N_NEUR + n];
    float e   = x0[4 * N_NEUR + n];
    float f   = x0[5 * N_NEUR + n];
    float cac = x0[6 * N_NEUR + n];

    const float* inj = i_inj + n;
    float* o = out + n;

    // ---- prefetch UNROLL currents (.ca so the replica hits L2; MLP=10)
    float cur[UNROLL];
    #pragma unroll
    for (int u = 0; u < UNROLL; ++u)
        cur[u] = __ldg(inj + u * N_NEUR);
    inj += UNROLL * N_NEUR;

    #pragma unroll 1
    for (int blk = 0; blk < NBLK; ++blk) {
        float nxt[UNROLL];
        if (blk < NBLK - 1) {
            #pragma unroll
            for (int u = 0; u < UNROLL; ++u)
                nxt[u] = __ldg(inj + u * N_NEUR);
            inj += UNROLL * N_NEUR;
        }

        #pragma unroll
        for (int u = 0; u < UNROLL; ++u) {
            const float icur = cur[u];

            // h from OLD cac
            const float h = fmaf(hb, fast_tanh(fmaf(cac, hc1, hc0)), ha);

            const float gef  = g_Ca * e * e * f * h;
            const float i_ca = gef * (V - E_Ca);
            const float VmEK = V - E_K;
            const float i_ks = g_Ks * nn * VmEK;
            const float p2   = p * p;
            const float i_kf = g_Kf * p2 * p2 * q * VmEK;
            const float i_l  = g_L * (V - E_L);

            const float itot = icur - ((i_ca + i_ks) + (i_kf + i_l));
            const float dV   = itot * dtCm;
            V += dV;

            // i_ca2 = gef*(V_new - E_Ca) = i_ca + gef*dV
            const float i_ca2 = fmaf(gef, dV, i_ca);
            cac = fmaf(cac, cdec, -i_ca2 * rhoDt);

            // 5 independent gate chains on UPDATED V
            p  = fmaf(Bp, fast_tanh(fmaf(V, pc1, pc0)), fmaf(Ap, p,  Bp));
            q  = fmaf(Bq, fast_tanh(fmaf(V, qc1, qc0)), fmaf(Aq, q,  Bq));
            e  = fmaf(Be, fast_tanh(fmaf(V, ec1, ec0)), fmaf(Ae, e,  Be));
            f  = fmaf(Bf, fast_tanh(fmaf(V, fc1, fc0)), fmaf(Af, f,  Bf));
            nn = fmaf(Bn, fast_tanh(fmaf(V, nc1, nc0)), fmaf(An, nn, Bn));

            // role-split streaming stores
            if (store_lo) {
                __stcs(o + 0 * N_NEUR, V);
                __stcs(o + 1 * N_NEUR, p);
                __stcs(o + 2 * N_NEUR, q);
                __stcs(o + 3 * N_NEUR, nn);
            }
            if (store_hi) {
                __stcs(o + 4 * N_NEUR, e);
                __stcs(o + 5 * N_NEUR, f);
                __stcs(o + 6 * N_NEUR, cac);
            }
            o += 7 * N_NEUR;
        }

        #pragma unroll
        for (int u = 0; u < UNROLL; ++u)
            cur[u] = nxt[u];
    }
}

extern "C" void kernel_launch(void* const* d_in, const int* in_sizes, int n_in,
                              void* d_out, int out_size) {
    const float* i_inj  = (const float*)d_in[0];
    const float* x0     = (const float*)d_in[1];
    const float* params = (const float*)d_in[2];
    float* out = (float*)d_out;

    // 1184 one-warp blocks = 625 groups + 559 replicas
    // -> exactly 8 blocks/SM, 2 warps/SMSP, zero imbalance
    hh_kernel<<<NGRP + NDUP, 32>>>(i_inj, x0, params, out);
}